// round 16
// baseline (speedup 1.0000x reference)
#include <cuda_runtime.h>

// Problem constants (fixed shapes: x (2,21,256,256), image (2,3,256,256))
#define NPT    131072          // 2*256*256 points
#define NC     21              // channels
#define HW     65536           // 256*256
#define DP1    6               // d+1
#define MAXLAT (NPT*DP1)       // 786432 max lattice points
#define CPAD   24              // padded channels per lattice row (96B rows)
#define HBITS  21
#define HSIZE  (1u<<HBITS)     // 2M slots
#define HMASK  (HSIZE-1u)
#define KEMPTY 0xFFFFFFFFFFFFFFFFull

#define XT_BLOCKS    4096      // transpose blocks (32 points each)
#define INIT_BLOCKS  2048
#define SPLAT_BLOCKS 4096      // 4 points/warp * 8 warps/block
#define NBR_BLOCKS   4736

// ---- static device scratch (no runtime allocation allowed) ----
__device__ unsigned long long g_hkeys[HSIZE];
__device__ int                g_hvals[HSIZE];
__device__ unsigned long long g_rowkey[MAXLAT];
__device__ int                g_slot[NPT*DP1];
__device__ int                g_idx[NPT*DP1];
__device__ float              g_bary[NPT*DP1];
__device__ int                g_nbr[MAXLAT*12];   // 6 dirs x (plus,minus) per row
__device__ __align__(256) float g_xt[NPT*CPAD];   // point-major x (24 floats/pt)
__device__ __align__(256) float g_lat0[MAXLAT*CPAD];
__device__ __align__(256) float g_lat1[MAXLAT*CPAD];
__device__ int                g_count;

__device__ __forceinline__ unsigned hhash(unsigned long long k){
    return (unsigned)((k * 0x9E3779B97F4A7C15ull) >> (64 - HBITS));
}

// Resume an insert whose first probe (slot s, value cur) was pre-loaded.
__device__ __forceinline__ int ht_insert_from(unsigned long long key,
                                              unsigned s, unsigned long long cur){
    while (true){
        if (cur == key) return (int)s;
        if (cur == KEMPTY){
            unsigned long long old = atomicCAS(&g_hkeys[s], KEMPTY, key);
            if (old == KEMPTY || old == key) return (int)s;
            cur = old;            // lost the race; re-examine this slot
            continue;
        }
        s = (s + 1) & HMASK;
        cur = g_hkeys[s];
    }
}

__device__ __forceinline__ int ht_lookup(unsigned long long key){
    unsigned s = hhash(key);
    while (true){
        unsigned long long cur = g_hkeys[s];
        if (cur == key) return g_hvals[s];
        if (cur == KEMPTY) return -1;
        s = (s + 1) & HMASK;
    }
}

__device__ __forceinline__ void red_add_v4(float* addr, float a, float b, float c, float d){
    asm volatile("red.global.add.v4.f32 [%0], {%1, %2, %3, %4};"
                 :: "l"(addr), "f"(a), "f"(b), "f"(c), "f"(d) : "memory");
}

// ---- K0 (fused): transpose x to point-major (blocks [0,XT_BLOCKS)) +
//                  reset hash table (rest) ----
__global__ void k_init(const float* __restrict__ x){
    if (blockIdx.x < XT_BLOCKS){
        __shared__ float sm[32][25];
        int n0 = blockIdx.x * 32;            // 32 consecutive points, same batch
        int b  = n0 >> 16;
        int hw0 = n0 & 65535;
        for (int t = threadIdx.x; t < NC*32; t += 256){
            int c = t >> 5, i = t & 31;
            sm[i][c] = x[(b*NC + c)*HW + hw0 + i];
        }
        for (int t = threadIdx.x; t < 3*32; t += 256){
            int c = 21 + (t >> 5), i = t & 31;
            sm[i][c] = 0.f;
        }
        __syncthreads();
        for (int t = threadIdx.x; t < 32*CPAD; t += 256){
            int i = t / CPAD, c = t - i*CPAD;
            g_xt[(n0 + i)*CPAD + c] = sm[i][c];
        }
    } else {
        unsigned bb = blockIdx.x - XT_BLOCKS;
        unsigned t = bb * blockDim.x + threadIdx.x;
        unsigned stride = INIT_BLOCKS * blockDim.x;
        ulonglong2 e = make_ulonglong2(KEMPTY, KEMPTY);
        ulonglong2* hp = (ulonglong2*)g_hkeys;
        for (unsigned i = t; i < HSIZE/2; i += stride) hp[i] = e;
        if (t == 0) g_count = 0;
    }
}

// ---- K1: per point: elevate, simplex, barycentric, batched key insert ----
__global__ void k_point(const float* __restrict__ img){
    int n = blockIdx.x * blockDim.x + threadIdx.x;
    if (n >= NPT) return;
    int b  = n >> 16;
    int hw = n & 65535;
    int h  = hw >> 8;
    int w  = hw & 255;

    const float* ip = img + b * 3 * HW + hw;
    float cf[5];
    cf[0] = ((float)w / 80.0f) * (float)3.4641016151377544;
    cf[1] = ((float)h / 80.0f) * (float)2.0;
    cf[2] = (ip[0]      / 13.0f) * (float)1.4142135623730951;
    cf[3] = (ip[HW]     / 13.0f) * (float)1.0954451150103321;
    cf[4] = (ip[2*HW]   / 13.0f) * (float)0.8944271909999159;

    float el[6];
    el[0] =  cf[0] + cf[1] + cf[2] + cf[3] + cf[4];
    el[1] = -1.f*cf[0] + cf[1] + cf[2] + cf[3] + cf[4];
    el[2] = -2.f*cf[1] + cf[2] + cf[3] + cf[4];
    el[3] = -3.f*cf[2] + cf[3] + cf[4];
    el[4] = -4.f*cf[3] + cf[4];
    el[5] = -5.f*cf[4];

    float rem0[6]; float s = 0.f;
#pragma unroll
    for (int j = 0; j < 6; j++){
        float v    = el[j] / 6.0f;
        float up   = ceilf(v)  * 6.0f;
        float down = floorf(v) * 6.0f;
        rem0[j] = ((up - el[j]) < (el[j] - down)) ? up : down;
        s += rem0[j];
    }
    int ssum = (int)rintf(s / 6.0f);

    float di[6];
#pragma unroll
    for (int j = 0; j < 6; j++) di[j] = el[j] - rem0[j];

    int rank[6];
#pragma unroll
    for (int i = 0; i < 6; i++){
        int r = 0;
#pragma unroll
        for (int j = 0; j < 6; j++){
            if (j == i) continue;
            if (j > i) r += (di[i] <  di[j]);
            else       r += (di[i] <= di[j]);
        }
        rank[i] = r + ssum;
    }
#pragma unroll
    for (int j = 0; j < 6; j++){
        if (rank[j] < 0)      { rank[j] += 6; rem0[j] += 6.f; }
        else if (rank[j] > 5) { rank[j] -= 6; rem0[j] -= 6.f; }
    }

    float bary[7] = {0.f,0.f,0.f,0.f,0.f,0.f,0.f};
#pragma unroll
    for (int i = 0; i < 6; i++){
        float t = (el[i] - rem0[i]) / 6.0f;
        bary[5 - rank[i]] += t;
        bary[6 - rank[i]] -= t;
    }
    bary[0] = (bary[0] + 1.0f) + bary[6];

    long long ri[5];
#pragma unroll
    for (int i = 0; i < 5; i++) ri[i] = (long long)llrintf(rem0[i]);

    // compute all 6 vertex keys, then issue all 6 first-probe loads (MLP=6)
    unsigned long long keys[6];
    unsigned           s0[6];
    unsigned long long cur[6];
#pragma unroll
    for (int r = 0; r < 6; r++){
        g_bary[n*DP1 + r] = bary[r];
        long long pk = ((long long)b) << 60;
#pragma unroll
        for (int i = 0; i < 5; i++){
            long long ki = ri[i] + r - ((rank[i] > 5 - r) ? 6 : 0);
            pk += (ki + 2048) << (12 * i);
        }
        keys[r] = (unsigned long long)pk;
        s0[r]   = hhash(keys[r]);
    }
#pragma unroll
    for (int r = 0; r < 6; r++) cur[r] = g_hkeys[s0[r]];   // independent loads
#pragma unroll
    for (int r = 0; r < 6; r++)
        g_slot[n*DP1 + r] = ht_insert_from(keys[r], s0[r], cur[r]);
}

// ---- K2: assign dense lattice indices + zero assigned rows ----
__global__ void k_assign(){
    const int SPT = 16;  // block covers 4096 slots
    __shared__ int wsum[8];
    __shared__ int blockBase;
    int t    = threadIdx.x;
    int base = blockIdx.x * (256 * SPT);

    int cnt = 0;
#pragma unroll
    for (int k = 0; k < SPT; k++)
        cnt += (g_hkeys[base + k*256 + t] != KEMPTY) ? 1 : 0;

    int lane = t & 31, wid = t >> 5;
    int pref = cnt;
#pragma unroll
    for (int off = 1; off < 32; off <<= 1){
        int y = __shfl_up_sync(0xffffffffu, pref, off);
        if (lane >= off) pref += y;
    }
    if (lane == 31) wsum[wid] = pref;
    __syncthreads();
    if (t < 8){
        int v = wsum[t];
#pragma unroll
        for (int off = 1; off < 8; off <<= 1){
            int y = __shfl_up_sync(0xffu, v, off);
            if (t >= off) v += y;
        }
        wsum[t] = v;
    }
    __syncthreads();
    if (t == 0) blockBase = atomicAdd(&g_count, wsum[7]);
    __syncthreads();

    int idx = blockBase + (wid ? wsum[wid-1] : 0) + (pref - cnt);
    float4 z = make_float4(0.f,0.f,0.f,0.f);
    float4* latp = (float4*)g_lat0;
    for (int k = 0; k < SPT; k++){
        int sIdx = base + k*256 + t;
        unsigned long long key = g_hkeys[sIdx];
        if (key != KEMPTY){
            g_hvals[sIdx]  = idx;
            g_rowkey[idx]  = key;
#pragma unroll
            for (int c = 0; c < 6; c++) latp[idx*6 + c] = z;
            idx++;
        }
    }
}

// ---- K3 (fused): splat v4 (blocks [0,SPLAT_BLOCKS)) + nbr precompute ----
__global__ void k_splat_nbr(){
    int lane = threadIdx.x & 31;

    if (blockIdx.x < SPLAT_BLOCKS){
        // ---- splat: warp handles 4 points; lane = (point p, chunk c) ----
        int gw = (blockIdx.x * blockDim.x + threadIdx.x) >> 5;
        int p  = lane / 6;          // 0..3 valid (lanes 0..23)
        int c  = lane - p * 6;      // float4 chunk 0..5
        bool act = lane < 24;
        int n = gw * 4 + p;         // point id (valid when act)

        float4 val = make_float4(0.f,0.f,0.f,0.f);
        int   myidx = 0;
        float myb   = 0.f;
        if (act){
            val = *(const float4*)&g_xt[n*CPAD + c*4];
            int slot = g_slot[n*DP1 + c];
            myidx = g_hvals[slot];
            g_idx[n*DP1 + c] = myidx;
            myb   = g_bary[n*DP1 + c];
        }
#pragma unroll
        for (int r = 0; r < DP1; r++){
            int src = p * 6 + r;
            int   idx = __shfl_sync(0xffffffffu, myidx, src);
            float wgt = __shfl_sync(0xffffffffu, myb,   src);
            if (act){
                red_add_v4(&g_lat0[idx*CPAD + c*4],
                           wgt*val.x, wgt*val.y, wgt*val.z, wgt*val.w);
            }
        }
    } else {
        // ---- nbr: flat item-parallel, 32/32 lanes, 3 independent probes ----
        int bb     = blockIdx.x - SPLAT_BLOCKS;
        int warp   = (bb * blockDim.x + threadIdx.x) >> 5;
        int nwarps = (NBR_BLOCKS * blockDim.x) >> 5;
        int U12 = g_count * 12;

        const long long ONES = 0x0001001001001001LL;  // +1 in each coord field

        for (int base = warp * 96; base < U12; base += nwarps * 96){
#pragma unroll
            for (int k = 0; k < 3; k++){
                int e = base + k*32 + lane;
                if (e < U12){
                    int i = e / 12;            // row (mul-shift division)
                    int l = e - i * 12;        // probe id 0..11
                    int j    = l >> 1;         // direction 0..5
                    int sgn  = l & 1;          // 0 = +d1, 1 = -d1
                    long long delta = (j < 5) ? (6LL << (12 * j)) : 0LL;
                    long long d1 = ONES - delta;
                    unsigned long long key = g_rowkey[i];
                    unsigned long long q = sgn ? (key - (unsigned long long)d1)
                                               : (key + (unsigned long long)d1);
                    g_nbr[e] = ht_lookup(q);
                }
            }
        }
    }
}

// ---- K4: blur pass j; warp handles 5 rows via float4 lanes (30/32 active) ----
__global__ void k_blur(int j){
    const float4* __restrict__ in  = (const float4*)((j & 1) ? g_lat1 : g_lat0);
    float4* __restrict__       out = (float4*)((j & 1) ? g_lat0 : g_lat1);
    int lane   = threadIdx.x & 31;
    int warp   = (blockIdx.x * blockDim.x + threadIdx.x) >> 5;
    int nwarps = (gridDim.x * blockDim.x) >> 5;
    int U = g_count;

    const int2* __restrict__ nbr = (const int2*)g_nbr;
    int r = lane / 6;           // row within group: 0..4 valid (lanes 0..29)
    int c = lane - r * 6;       // float4 chunk within row (0..5)
    bool act = lane < 30;

    for (int i0 = warp * 5; i0 < U; i0 += nwarps * 5){
        int i = i0 + r;
        if (act && i < U){
            int2 nn = __ldg(&nbr[i*6 + j]);     // 6 lanes/row share; rows consecutive
            float4 a = in[i*6 + c];             // contiguous 480B across the warp
            float4 s = make_float4(0.f, 0.f, 0.f, 0.f);
            if (nn.x >= 0){
                float4 v = in[nn.x*6 + c];
                s.x = v.x; s.y = v.y; s.z = v.z; s.w = v.w;
            }
            if (nn.y >= 0){
                float4 v = in[nn.y*6 + c];
                s.x += v.x; s.y += v.y; s.z += v.z; s.w += v.w;
            }
            float4 o;
            o.x = a.x + 0.5f * s.x;
            o.y = a.y + 0.5f * s.y;
            o.z = a.z + 0.5f * s.z;
            o.w = a.w + 0.5f * s.w;
            out[i*6 + c] = o;
        }
    }
}

// ---- K5: slice (float4 gather, 4 points/warp) + transpose to NCHW ----
__global__ void k_slice(float* __restrict__ out){
    __shared__ float sm[32][25];
    int warp = threadIdx.x >> 5, lane = threadIdx.x & 31;
    int n0 = blockIdx.x * 32;
    const float ALPHA = (float)(32.0 / 33.0);  // 1/(1+2^-5)

    int p  = lane / 6;          // local point within warp group (0..3 valid)
    int c  = lane - p * 6;      // float4 chunk 0..5
    bool act = lane < 24;
    int il = warp * 4 + p;      // local point 0..31
    int n  = n0 + il;           // global point

    int   myidx = 0;
    float myb   = 0.f;
    if (act){
        myidx = g_idx[n*DP1 + c];
        myb   = g_bary[n*DP1 + c];
    }
    float4 acc = make_float4(0.f, 0.f, 0.f, 0.f);
#pragma unroll
    for (int r = 0; r < DP1; r++){
        int src = p * 6 + r;
        int   idx = __shfl_sync(0xffffffffu, myidx, src);
        float bw  = __shfl_sync(0xffffffffu, myb,   src);
        if (act){
            float4 v = *(const float4*)&g_lat0[idx*CPAD + c*4];
            acc.x += bw * v.x;
            acc.y += bw * v.y;
            acc.z += bw * v.z;
            acc.w += bw * v.w;
        }
    }
    if (act){
        sm[il][c*4 + 0] = ALPHA * acc.x;
        sm[il][c*4 + 1] = ALPHA * acc.y;
        sm[il][c*4 + 2] = ALPHA * acc.z;
        sm[il][c*4 + 3] = ALPHA * acc.w;
    }
    __syncthreads();

    for (int t = threadIdx.x; t < NC * 32; t += 256){
        int cc = t >> 5, i = t & 31;
        int nn = n0 + i;
        int b  = nn >> 16;
        int hw = nn & 65535;
        out[(b*NC + cc) * HW + hw] = sm[i][cc];
    }
}

extern "C" void kernel_launch(void* const* d_in, const int* in_sizes, int n_in,
                              void* d_out, int out_size){
    const float* x   = (const float*)d_in[0];   // (2,21,256,256)
    const float* img = (const float*)d_in[1];   // (2,3,256,256)
    float* out = (float*)d_out;

    k_init     <<<XT_BLOCKS + INIT_BLOCKS, 256>>>(x);
    k_point    <<<NPT/256, 256>>>(img);
    k_assign   <<<HSIZE/(256*16), 256>>>();
    k_splat_nbr<<<SPLAT_BLOCKS + NBR_BLOCKS, 256>>>();
    for (int j = 0; j < 6; j++)
        k_blur<<<4736, 256>>>(j);
    k_slice    <<<NPT/32, 256>>>(out);
}

// round 17
// speedup vs baseline: 1.0328x; 1.0328x over previous
#include <cuda_runtime.h>

// Problem constants (fixed shapes: x (2,21,256,256), image (2,3,256,256))
#define NPT    131072          // 2*256*256 points
#define NC     21              // channels
#define HW     65536           // 256*256
#define DP1    6               // d+1
#define MAXLAT (NPT*DP1)       // 786432 max lattice points
#define CPAD   24              // padded channels per lattice row (96B rows)
#define HBITS  21
#define HSIZE  (1u<<HBITS)     // 2M slots
#define HMASK  (HSIZE-1u)
#define KEMPTY 0xFFFFFFFFFFFFFFFFull

#define XT_BLOCKS    4096      // transpose blocks (32 points each)
#define INIT_BLOCKS  2048
#define SPLAT_BLOCKS 4096      // 4 points/warp * 8 warps/block
#define NBR_BLOCKS   4736

// ---- static device scratch (no runtime allocation allowed) ----
__device__ unsigned long long g_hkeys[HSIZE];
__device__ int                g_hvals[HSIZE];
__device__ unsigned long long g_rowkey[MAXLAT];
__device__ int                g_slot[NPT*DP1];
__device__ int                g_idx[NPT*DP1];
__device__ float              g_bary[NPT*DP1];
__device__ int                g_nbr[MAXLAT*12];   // 6 dirs x (plus,minus) per row
__device__ __align__(256) float g_xt[NPT*CPAD];   // point-major x (24 floats/pt)
__device__ __align__(256) float g_lat0[MAXLAT*CPAD];
__device__ __align__(256) float g_lat1[MAXLAT*CPAD];
__device__ int                g_count;

__device__ __forceinline__ unsigned hhash(unsigned long long k){
    return (unsigned)((k * 0x9E3779B97F4A7C15ull) >> (64 - HBITS));
}

__device__ __forceinline__ int ht_insert(unsigned long long key){
    unsigned s = hhash(key);
    while (true){
        unsigned long long cur = g_hkeys[s];
        if (cur == key) return (int)s;
        if (cur == KEMPTY){
            unsigned long long old = atomicCAS(&g_hkeys[s], KEMPTY, key);
            if (old == KEMPTY || old == key) return (int)s;
        }
        s = (s + 1) & HMASK;
    }
}

__device__ __forceinline__ int ht_lookup(unsigned long long key){
    unsigned s = hhash(key);
    while (true){
        unsigned long long cur = g_hkeys[s];
        if (cur == key) return g_hvals[s];
        if (cur == KEMPTY) return -1;
        s = (s + 1) & HMASK;
    }
}

__device__ __forceinline__ void red_add_v4(float* addr, float a, float b, float c, float d){
    asm volatile("red.global.add.v4.f32 [%0], {%1, %2, %3, %4};"
                 :: "l"(addr), "f"(a), "f"(b), "f"(c), "f"(d) : "memory");
}

// ---- K0 (fused): transpose x to point-major (blocks [0,XT_BLOCKS)) +
//                  reset hash table (rest) ----
__global__ void k_init(const float* __restrict__ x){
    if (blockIdx.x < XT_BLOCKS){
        __shared__ float sm[32][25];
        int n0 = blockIdx.x * 32;            // 32 consecutive points, same batch
        int b  = n0 >> 16;
        int hw0 = n0 & 65535;
        for (int t = threadIdx.x; t < NC*32; t += 256){
            int c = t >> 5, i = t & 31;
            sm[i][c] = x[(b*NC + c)*HW + hw0 + i];
        }
        for (int t = threadIdx.x; t < 3*32; t += 256){
            int c = 21 + (t >> 5), i = t & 31;
            sm[i][c] = 0.f;
        }
        __syncthreads();
        for (int t = threadIdx.x; t < 32*CPAD; t += 256){
            int i = t / CPAD, c = t - i*CPAD;
            g_xt[(n0 + i)*CPAD + c] = sm[i][c];
        }
    } else {
        unsigned bb = blockIdx.x - XT_BLOCKS;
        unsigned t = bb * blockDim.x + threadIdx.x;
        unsigned stride = INIT_BLOCKS * blockDim.x;
        ulonglong2 e = make_ulonglong2(KEMPTY, KEMPTY);
        ulonglong2* hp = (ulonglong2*)g_hkeys;
        for (unsigned i = t; i < HSIZE/2; i += stride) hp[i] = e;
        if (t == 0) g_count = 0;
    }
}

// ---- K1: per point: elevate, simplex, barycentric, key insert ----
__global__ void k_point(const float* __restrict__ img){
    int n = blockIdx.x * blockDim.x + threadIdx.x;
    if (n >= NPT) return;
    int b  = n >> 16;
    int hw = n & 65535;
    int h  = hw >> 8;
    int w  = hw & 255;

    const float* ip = img + b * 3 * HW + hw;
    float cf[5];
    cf[0] = ((float)w / 80.0f) * (float)3.4641016151377544;
    cf[1] = ((float)h / 80.0f) * (float)2.0;
    cf[2] = (ip[0]      / 13.0f) * (float)1.4142135623730951;
    cf[3] = (ip[HW]     / 13.0f) * (float)1.0954451150103321;
    cf[4] = (ip[2*HW]   / 13.0f) * (float)0.8944271909999159;

    float el[6];
    el[0] =  cf[0] + cf[1] + cf[2] + cf[3] + cf[4];
    el[1] = -1.f*cf[0] + cf[1] + cf[2] + cf[3] + cf[4];
    el[2] = -2.f*cf[1] + cf[2] + cf[3] + cf[4];
    el[3] = -3.f*cf[2] + cf[3] + cf[4];
    el[4] = -4.f*cf[3] + cf[4];
    el[5] = -5.f*cf[4];

    float rem0[6]; float s = 0.f;
#pragma unroll
    for (int j = 0; j < 6; j++){
        float v    = el[j] / 6.0f;
        float up   = ceilf(v)  * 6.0f;
        float down = floorf(v) * 6.0f;
        rem0[j] = ((up - el[j]) < (el[j] - down)) ? up : down;
        s += rem0[j];
    }
    int ssum = (int)rintf(s / 6.0f);

    float di[6];
#pragma unroll
    for (int j = 0; j < 6; j++) di[j] = el[j] - rem0[j];

    int rank[6];
#pragma unroll
    for (int i = 0; i < 6; i++){
        int r = 0;
#pragma unroll
        for (int j = 0; j < 6; j++){
            if (j == i) continue;
            if (j > i) r += (di[i] <  di[j]);
            else       r += (di[i] <= di[j]);
        }
        rank[i] = r + ssum;
    }
#pragma unroll
    for (int j = 0; j < 6; j++){
        if (rank[j] < 0)      { rank[j] += 6; rem0[j] += 6.f; }
        else if (rank[j] > 5) { rank[j] -= 6; rem0[j] -= 6.f; }
    }

    float bary[7] = {0.f,0.f,0.f,0.f,0.f,0.f,0.f};
#pragma unroll
    for (int i = 0; i < 6; i++){
        float t = (el[i] - rem0[i]) / 6.0f;
        bary[5 - rank[i]] += t;
        bary[6 - rank[i]] -= t;
    }
    bary[0] = (bary[0] + 1.0f) + bary[6];

    long long ri[5];
#pragma unroll
    for (int i = 0; i < 5; i++) ri[i] = (long long)llrintf(rem0[i]);

#pragma unroll
    for (int r = 0; r < 6; r++){
        g_bary[n*DP1 + r] = bary[r];
        long long pk = ((long long)b) << 60;
#pragma unroll
        for (int i = 0; i < 5; i++){
            long long ki = ri[i] + r - ((rank[i] > 5 - r) ? 6 : 0);
            pk += (ki + 2048) << (12 * i);
        }
        g_slot[n*DP1 + r] = ht_insert((unsigned long long)pk);
    }
}

// ---- K2: assign dense lattice indices + zero assigned rows (SPT=4) ----
__global__ void k_assign(){
    const int SPT = 4;   // block covers 1024 slots; 2048 blocks total
    __shared__ int wsum[8];
    __shared__ int blockBase;
    int t    = threadIdx.x;
    int base = blockIdx.x * (256 * SPT);

    int cnt = 0;
#pragma unroll
    for (int k = 0; k < SPT; k++)
        cnt += (g_hkeys[base + k*256 + t] != KEMPTY) ? 1 : 0;

    int lane = t & 31, wid = t >> 5;
    int pref = cnt;
#pragma unroll
    for (int off = 1; off < 32; off <<= 1){
        int y = __shfl_up_sync(0xffffffffu, pref, off);
        if (lane >= off) pref += y;
    }
    if (lane == 31) wsum[wid] = pref;
    __syncthreads();
    if (t < 8){
        int v = wsum[t];
#pragma unroll
        for (int off = 1; off < 8; off <<= 1){
            int y = __shfl_up_sync(0xffu, v, off);
            if (t >= off) v += y;
        }
        wsum[t] = v;
    }
    __syncthreads();
    if (t == 0) blockBase = atomicAdd(&g_count, wsum[7]);
    __syncthreads();

    int idx = blockBase + (wid ? wsum[wid-1] : 0) + (pref - cnt);
    float4 z = make_float4(0.f,0.f,0.f,0.f);
    float4* latp = (float4*)g_lat0;
#pragma unroll
    for (int k = 0; k < SPT; k++){
        int sIdx = base + k*256 + t;
        unsigned long long key = g_hkeys[sIdx];
        if (key != KEMPTY){
            g_hvals[sIdx]  = idx;
            g_rowkey[idx]  = key;
#pragma unroll
            for (int c = 0; c < 6; c++) latp[idx*6 + c] = z;
            idx++;
        }
    }
}

// ---- K3 (fused): splat v4 (blocks [0,SPLAT_BLOCKS)) + nbr precompute ----
__global__ void k_splat_nbr(){
    int lane = threadIdx.x & 31;

    if (blockIdx.x < SPLAT_BLOCKS){
        // ---- splat: warp handles 4 points; lane = (point p, chunk c) ----
        int gw = (blockIdx.x * blockDim.x + threadIdx.x) >> 5;
        int p  = lane / 6;          // 0..3 valid (lanes 0..23)
        int c  = lane - p * 6;      // float4 chunk 0..5
        bool act = lane < 24;
        int n = gw * 4 + p;         // point id (valid when act)

        float4 val = make_float4(0.f,0.f,0.f,0.f);
        int   myidx = 0;
        float myb   = 0.f;
        if (act){
            val = *(const float4*)&g_xt[n*CPAD + c*4];
            int slot = g_slot[n*DP1 + c];
            myidx = g_hvals[slot];
            g_idx[n*DP1 + c] = myidx;
            myb   = g_bary[n*DP1 + c];
        }
#pragma unroll
        for (int r = 0; r < DP1; r++){
            int src = p * 6 + r;
            int   idx = __shfl_sync(0xffffffffu, myidx, src);
            float wgt = __shfl_sync(0xffffffffu, myb,   src);
            if (act){
                red_add_v4(&g_lat0[idx*CPAD + c*4],
                           wgt*val.x, wgt*val.y, wgt*val.z, wgt*val.w);
            }
        }
    } else {
        // ---- nbr: flat item-parallel, 32/32 lanes, 3 independent probes ----
        int bb     = blockIdx.x - SPLAT_BLOCKS;
        int warp   = (bb * blockDim.x + threadIdx.x) >> 5;
        int nwarps = (NBR_BLOCKS * blockDim.x) >> 5;
        int U12 = g_count * 12;

        const long long ONES = 0x0001001001001001LL;  // +1 in each coord field

        for (int base = warp * 96; base < U12; base += nwarps * 96){
#pragma unroll
            for (int k = 0; k < 3; k++){
                int e = base + k*32 + lane;
                if (e < U12){
                    int i = e / 12;            // row (mul-shift division)
                    int l = e - i * 12;        // probe id 0..11
                    int j    = l >> 1;         // direction 0..5
                    int sgn  = l & 1;          // 0 = +d1, 1 = -d1
                    long long delta = (j < 5) ? (6LL << (12 * j)) : 0LL;
                    long long d1 = ONES - delta;
                    unsigned long long key = g_rowkey[i];
                    unsigned long long q = sgn ? (key - (unsigned long long)d1)
                                               : (key + (unsigned long long)d1);
                    g_nbr[e] = ht_lookup(q);
                }
            }
        }
    }
}

// ---- K4: blur pass j; warp handles 5 rows via float4 lanes (30/32 active) ----
__global__ void k_blur(int j){
    const float4* __restrict__ in  = (const float4*)((j & 1) ? g_lat1 : g_lat0);
    float4* __restrict__       out = (float4*)((j & 1) ? g_lat0 : g_lat1);
    int lane   = threadIdx.x & 31;
    int warp   = (blockIdx.x * blockDim.x + threadIdx.x) >> 5;
    int nwarps = (gridDim.x * blockDim.x) >> 5;
    int U = g_count;

    const int2* __restrict__ nbr = (const int2*)g_nbr;
    int r = lane / 6;           // row within group: 0..4 valid (lanes 0..29)
    int c = lane - r * 6;       // float4 chunk within row (0..5)
    bool act = lane < 30;

    for (int i0 = warp * 5; i0 < U; i0 += nwarps * 5){
        int i = i0 + r;
        if (act && i < U){
            int2 nn = __ldg(&nbr[i*6 + j]);     // 6 lanes/row share; rows consecutive
            float4 a = in[i*6 + c];             // contiguous 480B across the warp
            float4 s = make_float4(0.f, 0.f, 0.f, 0.f);
            if (nn.x >= 0){
                float4 v = in[nn.x*6 + c];
                s.x = v.x; s.y = v.y; s.z = v.z; s.w = v.w;
            }
            if (nn.y >= 0){
                float4 v = in[nn.y*6 + c];
                s.x += v.x; s.y += v.y; s.z += v.z; s.w += v.w;
            }
            float4 o;
            o.x = a.x + 0.5f * s.x;
            o.y = a.y + 0.5f * s.y;
            o.z = a.z + 0.5f * s.z;
            o.w = a.w + 0.5f * s.w;
            out[i*6 + c] = o;
        }
    }
}

// ---- K5: slice (float4 gather, 4 points/warp) + transpose to NCHW ----
__global__ void k_slice(float* __restrict__ out){
    __shared__ float sm[32][25];
    int warp = threadIdx.x >> 5, lane = threadIdx.x & 31;
    int n0 = blockIdx.x * 32;
    const float ALPHA = (float)(32.0 / 33.0);  // 1/(1+2^-5)

    int p  = lane / 6;          // local point within warp group (0..3 valid)
    int c  = lane - p * 6;      // float4 chunk 0..5
    bool act = lane < 24;
    int il = warp * 4 + p;      // local point 0..31
    int n  = n0 + il;           // global point

    int   myidx = 0;
    float myb   = 0.f;
    if (act){
        myidx = g_idx[n*DP1 + c];
        myb   = g_bary[n*DP1 + c];
    }
    float4 acc = make_float4(0.f, 0.f, 0.f, 0.f);
#pragma unroll
    for (int r = 0; r < DP1; r++){
        int src = p * 6 + r;
        int   idx = __shfl_sync(0xffffffffu, myidx, src);
        float bw  = __shfl_sync(0xffffffffu, myb,   src);
        if (act){
            float4 v = *(const float4*)&g_lat0[idx*CPAD + c*4];
            acc.x += bw * v.x;
            acc.y += bw * v.y;
            acc.z += bw * v.z;
            acc.w += bw * v.w;
        }
    }
    if (act){
        sm[il][c*4 + 0] = ALPHA * acc.x;
        sm[il][c*4 + 1] = ALPHA * acc.y;
        sm[il][c*4 + 2] = ALPHA * acc.z;
        sm[il][c*4 + 3] = ALPHA * acc.w;
    }
    __syncthreads();

    for (int t = threadIdx.x; t < NC * 32; t += 256){
        int cc = t >> 5, i = t & 31;
        int nn = n0 + i;
        int b  = nn >> 16;
        int hw = nn & 65535;
        out[(b*NC + cc) * HW + hw] = sm[i][cc];
    }
}

extern "C" void kernel_launch(void* const* d_in, const int* in_sizes, int n_in,
                              void* d_out, int out_size){
    const float* x   = (const float*)d_in[0];   // (2,21,256,256)
    const float* img = (const float*)d_in[1];   // (2,3,256,256)
    float* out = (float*)d_out;

    k_init     <<<XT_BLOCKS + INIT_BLOCKS, 256>>>(x);
    k_point    <<<NPT/256, 256>>>(img);
    k_assign   <<<HSIZE/(256*4), 256>>>();
    k_splat_nbr<<<SPLAT_BLOCKS + NBR_BLOCKS, 256>>>();
    for (int j = 0; j < 6; j++)
        k_blur<<<4736, 256>>>(j);
    k_slice    <<<NPT/32, 256>>>(out);
}